// round 8
// baseline (speedup 1.0000x reference)
#include <cuda_runtime.h>
#include <cuda_fp16.h>
#include <math.h>

// ---------------- problem constants ----------------
#define NF     1044
#define VOCAB  9396                 // NF * 9
#define CH     116                  // fields per chunk (1044 = 9*116) = 29 float4
#define NCH    9
#define ROWB   80                   // 32 fp16 + fp32 lin + pad (16B aligned!)
#define FSTRIDE 720                 // 9*ROWB
#define TBL_CH (CH*FSTRIDE)         // 83520 bytes per chunk
#define IDX_OFF (2*TBL_CH)          // 167040
#define IDXROW  60                  // bytes per sample per chunk (58 used)
#define IDXBUF  (128*IDXROW)        // 7680
#define MBAR_OFF (IDX_OFF + 2*IDXBUF)      // 182400 (16-aligned)
#define PRM_OFF  (MBAR_OFF + 16)           // 182416
#define SMEM_SZ  (PRM_OFF + 4624)          // 187040 (<= 232448)
#define NELEM    3712                      // 128 samples * 29 float4
#define BN_INV  0.9999950000374997f        // 1/sqrt(1+1e-5)

// fused table: [VOCAB][80B] = {32 x fp16 (emb row @ w1 block), fp32 w_lin, pad}
__device__ __align__(16) unsigned char g_tbl[VOCAB * ROWB];

// ---------------- pass 0: build fused table ----------------
__global__ void build_table(const float* __restrict__ emb,
                            const float* __restrict__ w1,
                            const float* __restrict__ w_lin) {
    int warp = (blockIdx.x * blockDim.x + threadIdx.x) >> 5;
    int lane = threadIdx.x & 31;
    if (warp >= NF) return;
    int f = warp;
    float wa = w1[(f*4+0)*32 + lane];
    float wb = w1[(f*4+1)*32 + lane];
    float wc = w1[(f*4+2)*32 + lane];
    float wd = w1[(f*4+3)*32 + lane];
    #pragma unroll
    for (int v = 0; v < 9; v++) {
        int gi = f*9 + v;
        const float* e = emb + gi*4;
        float s = e[0]*wa + e[1]*wb + e[2]*wc + e[3]*wd;
        char* row = (char*)g_tbl + gi*ROWB;
        ((__half*)row)[lane] = __float2half_rn(s);
        if (lane == 0) *(float*)(row + 64) = w_lin[gi];
    }
}

// ---------------- mbarrier + TMA bulk helpers ----------------
__device__ __forceinline__ void mbar_init(unsigned m, unsigned cnt) {
    asm volatile("mbarrier.init.shared.b64 [%0], %1;" :: "r"(m), "r"(cnt) : "memory");
}
__device__ __forceinline__ void mbar_expect_tx(unsigned m, unsigned bytes) {
    asm volatile("mbarrier.arrive.expect_tx.shared.b64 _, [%0], %1;"
                 :: "r"(m), "r"(bytes) : "memory");
}
__device__ __forceinline__ void bulk_g2s(unsigned dst, const void* src,
                                         unsigned bytes, unsigned m) {
    asm volatile("cp.async.bulk.shared::cta.global.mbarrier::complete_tx::bytes "
                 "[%0], [%1], %2, [%3];"
                 :: "r"(dst), "l"(src), "r"(bytes), "r"(m) : "memory");
}
__device__ __forceinline__ void mbar_wait(unsigned m, unsigned parity) {
    asm volatile(
        "{\n\t.reg .pred P;\n"
        "WL%=:\n\t"
        "mbarrier.try_wait.parity.acquire.cta.shared::cta.b64 P, [%0], %1, 0x989680;\n\t"
        "@!P bra WL%=;\n\t}"
        :: "r"(m), "r"(parity) : "memory");
}

// reference semantics: x > 5.0 -> 8, else (int)(x + 2.0)
__device__ __forceinline__ int bucket(float x) {
    return (x > 5.0f) ? 8 : (int)(x + 2.0f);
}

// one field: 16B slice via LDS.128, 4 HADD2
#define GF(vv, FOFS) {                                                     \
    uint4 d = *(const uint4*)(fb + (FOFS) + (int)(vv)*80);                 \
    a0 = __hadd2(a0, *(const __half2*)&d.x);                               \
    a1 = __hadd2(a1, *(const __half2*)&d.y);                               \
    a2 = __hadd2(a2, *(const __half2*)&d.z);                               \
    a3 = __hadd2(a3, *(const __half2*)&d.w); }

// 4 fields from one 16-bit nibble group
#define G4W(P, BASE) {                                                     \
    unsigned _p = (P);                                                     \
    GF(_p & 15u, (BASE));                                                  \
    GF((_p >> 4) & 15u, (BASE) + 720);                                     \
    GF((_p >> 8) & 15u, (BASE) + 1440);                                    \
    GF((_p >> 12) & 15u, (BASE) + 2160); }

__global__ void __launch_bounds__(1024, 1)
fused_kernel(const float* __restrict__ state,
             const float* __restrict__ b1,  const float* __restrict__ g1,
             const float* __restrict__ be1,
             const float* __restrict__ w2,  const float* __restrict__ b2,
             const float* __restrict__ g2,  const float* __restrict__ be2,
             const float* __restrict__ w3,  const float* __restrict__ b3,
             const float* __restrict__ b_lin,
             float* __restrict__ out) {
    extern __shared__ char smem[];
    const int tid  = threadIdx.x;
    const int slot = tid & 127;        // sample within block
    const int g    = (tid >> 7) & 3;   // 16B output slice 0..3
    const int h    = tid >> 9;         // field half 0..1
    const int gh   = (g << 1) | h;     // 0..7
    const int s0   = blockIdx.x * 128;
    float* prm = (float*)(smem + PRM_OFF);
    const unsigned smem_u32 = (unsigned)__cvta_generic_to_shared(smem);
    const unsigned mbar0 = smem_u32 + MBAR_OFF;
    const unsigned mbar1 = smem_u32 + MBAR_OFF + 8;

    if (tid == 0) { mbar_init(mbar0, 1); mbar_init(mbar1, 1); }
    __syncthreads();
    // prefetch table chunks 0 and 1 via TMA bulk (overlaps staging below)
    if (tid == 0) {
        mbar_expect_tx(mbar0, TBL_CH);
        bulk_g2s(smem_u32, (const char*)g_tbl, TBL_CH, mbar0);
        mbar_expect_tx(mbar1, TBL_CH);
        bulk_g2s(smem_u32 + TBL_CH, (const char*)g_tbl + TBL_CH, TBL_CH, mbar1);
    }

    // stage idx chunk 0 (nibble-packed: float4 -> uint16)
    {
        char* dstb = smem + IDX_OFF;
        for (int e = tid; e < NELEM; e += 1024) {
            int r = e / 29, u = e - r*29;
            float4 xv = *(const float4*)(state + (size_t)(s0 + r)*NF + u*4);
            int v0 = bucket(xv.x), v1 = bucket(xv.y);
            int v2 = bucket(xv.z), v3 = bucket(xv.w);
            *(unsigned short*)(dstb + r*IDXROW + u*2) =
                (unsigned short)(v0 | (v1<<4) | (v2<<8) | (v3<<12));
        }
    }
    // stage MLP params
    for (int i = tid; i < 1154; i += 1024) {
        float v;
        if (i < 1024)      v = w2[i];
        else if (i < 1056) v = b2[i-1024];
        else if (i < 1088) v = g2[i-1056];
        else if (i < 1120) v = be2[i-1088];
        else if (i < 1152) v = w3[i-1120];
        else if (i == 1152) v = b3[0];
        else               v = b_lin[0];
        prm[i] = v;
    }
    __syncthreads();

    __half2 a0 = __float2half2_rn(0.f), a1 = a0, a2 = a0, a3 = a0;
    float lin = 0.f;

    for (int c = 0; c < NCH; c++) {
        // stage idx for chunk c+1 (LDGs issue early, latency hides under gather)
        if (c + 1 < NCH) {
            char* dstb = smem + IDX_OFF + ((c+1)&1)*IDXBUF;
            const float* sbase = state + (size_t)s0*NF + (c+1)*CH;
            for (int e = tid; e < NELEM; e += 1024) {
                int r = e / 29, u = e - r*29;
                float4 xv = *(const float4*)(sbase + (size_t)r*NF + u*4);
                int v0 = bucket(xv.x), v1 = bucket(xv.y);
                int v2 = bucket(xv.z), v3 = bucket(xv.w);
                *(unsigned short*)(dstb + r*IDXROW + u*2) =
                    (unsigned short)(v0 | (v1<<4) | (v2<<8) | (v3<<12));
            }
        }

        // wait for this chunk's table transfer
        mbar_wait((c&1) ? mbar1 : mbar0, (c>>1)&1);

        const char* tbuf = smem + (c&1)*TBL_CH;
        const unsigned int* mi =
            (const unsigned int*)(smem + IDX_OFF + (c&1)*IDXBUF + slot*IDXROW);

        // gather: half h covers words [7h, 7h+7); h==0 also takes tail word 14
        {
            const char* fb = tbuf + g*16 + h*7*5760;
            const int wbase = h*7;
            #pragma unroll 2
            for (int w = 0; w < 7; w++) {
                unsigned int pk = mi[wbase + w];
                G4W(pk, 0);
                G4W(pk >> 16, 2880);
                fb += 5760;
            }
            if (h == 0) {
                fb = tbuf + g*16 + 14*5760;
                unsigned int pk = mi[14] & 0xffffu;
                G4W(pk, 0);
            }
        }

        // lin accumulation: bytes split across 8 (g,h) groups (2x8 + 6x7 = 58)
        {
            const unsigned char* bi = (const unsigned char*)mi;
            int lo = (gh < 2) ? gh*8 : 16 + (gh-2)*7;
            int nb = (gh < 2) ? 8 : 7;
            for (int b = lo; b < lo + nb; b++) {
                unsigned int pkb = bi[b];
                const char* fo = tbuf + b*1440 + 64;
                lin += *(const float*)(fo + (pkb & 15u)*80);
                lin += *(const float*)(fo + 720 + (pkb >> 4)*80);
            }
        }

        __syncthreads();   // idx(c+1) visible; table buf (c&1) drained

        // refill this table buffer with chunk c+2
        if (tid == 0 && c + 2 < NCH) {
            unsigned mb = (c&1) ? mbar1 : mbar0;
            mbar_expect_tx(mb, TBL_CH);
            bulk_g2s(smem_u32 + (c&1)*TBL_CH,
                     (const char*)g_tbl + (c+2)*TBL_CH, TBL_CH, mb);
        }
    }

    // ---------------- epilogue: BN1+ReLU, MLP, sigmoid ----------------
    // thread (slot,g,h) holds partial pre-activations for outputs g*8..g*8+7
    float2 p01 = __half22float2(a0);
    float2 p23 = __half22float2(a1);
    float2 p45 = __half22float2(a2);
    float2 p67 = __half22float2(a3);
    float pre[8] = {p01.x,p01.y,p23.x,p23.y,p45.x,p45.y,p67.x,p67.y};
    float* h1b = (float*)smem;   // reuse table region: [128][73]: 2x32 + 8 lin
    const int j0 = g*8;
    #pragma unroll
    for (int k = 0; k < 8; k++)
        h1b[slot*73 + h*32 + j0 + k] = pre[k];
    h1b[slot*73 + 64 + gh] = lin;
    __syncthreads();

    if (tid < 128) {
        const float* hr = h1b + tid*73;
        float linv = 0.f;
        #pragma unroll
        for (int i = 0; i < 8; i++) linv += hr[64 + i];
        float acc[32];
        #pragma unroll
        for (int j = 0; j < 32; j++) acc[j] = prm[1024 + j];   // b2
        for (int k = 0; k < 32; k++) {
            float sc = g1[k] * BN_INV;
            float hk = (hr[k] + hr[32+k])*sc + (b1[k]*sc + be1[k]);
            hk = fmaxf(hk, 0.f);                               // BN1 + ReLU
            #pragma unroll
            for (int j = 0; j < 32; j++) acc[j] += hk * prm[k*32 + j];  // w2
        }
        float x = prm[1152] + prm[1153] + linv;   // b3 + b_lin + lin
        #pragma unroll
        for (int j = 0; j < 32; j++) {
            float h2 = fmaxf(acc[j]*(prm[1056+j]*BN_INV) + prm[1088+j], 0.f);
            x += h2 * prm[1120+j];                // w3
        }
        out[s0 + tid] = 1.0f / (1.0f + expf(-x));
    }
}

// ---------------- launch ----------------
extern "C" void kernel_launch(void* const* d_in, const int* in_sizes, int n_in,
                              void* d_out, int out_size) {
    const float* state = (const float*)d_in[0];
    const float* w_lin = (const float*)d_in[1];
    const float* b_lin = (const float*)d_in[2];
    const float* emb   = (const float*)d_in[3];
    const float* w1    = (const float*)d_in[4];
    const float* b1    = (const float*)d_in[5];
    const float* g1    = (const float*)d_in[6];
    const float* be1   = (const float*)d_in[7];
    const float* w2    = (const float*)d_in[8];
    const float* b2    = (const float*)d_in[9];
    const float* g2    = (const float*)d_in[10];
    const float* be2   = (const float*)d_in[11];
    const float* w3    = (const float*)d_in[12];
    const float* b3    = (const float*)d_in[13];
    float* out = (float*)d_out;

    cudaFuncSetAttribute(fused_kernel,
                         cudaFuncAttributeMaxDynamicSharedMemorySize, SMEM_SZ);

    build_table<<<131, 256>>>(emb, w1, w_lin);
    fused_kernel<<<128, 1024, SMEM_SZ>>>(state, b1, g1, be1,
                                         w2, b2, g2, be2, w3, b3, b_lin, out);
}

// round 9
// speedup vs baseline: 1.0583x; 1.0583x over previous
#include <cuda_runtime.h>
#include <cuda_fp16.h>
#include <math.h>

// ---------------- problem constants ----------------
#define NF     1044
#define VOCAB  9396                 // NF * 9
#define CH     58                   // fields per chunk (1044 = 18*58)
#define NCH    18
#define ROWB   72                   // 32 fp16 + fp32 lin + 4B pad
#define FSTRIDE 648                 // 9*ROWB
#define TBL_CH (CH*FSTRIDE)         // 37584 bytes per chunk
#define IDX_OFF (2*TBL_CH)          // 75168
#define IDXROW  36                  // bytes per sample per chunk (29 used; 9 words, 9 coprime 32)
#define IDXBUF  (64*IDXROW)         // 2304
#define MBAR_OFF (IDX_OFF + 2*IDXBUF)      // 79776 (16-aligned)
#define PRM_OFF  (MBAR_OFF + 16)           // 79792
#define SMEM_SZ  (PRM_OFF + 4624)          // 84416  (2 CTAs/SM: 168832 <= 232448)
#define NELEM    1856                      // 64 samples * 29 float2
#define BN_INV  0.9999950000374997f        // 1/sqrt(1+1e-5)

// fused table: [VOCAB][72B] = {32 x fp16 (emb row @ w1 block), fp32 w_lin, pad}
__device__ __align__(16) unsigned char g_tbl[VOCAB * ROWB];

// ---------------- pass 0: build fused table ----------------
__global__ void build_table(const float* __restrict__ emb,
                            const float* __restrict__ w1,
                            const float* __restrict__ w_lin) {
    int warp = (blockIdx.x * blockDim.x + threadIdx.x) >> 5;
    int lane = threadIdx.x & 31;
    if (warp >= NF) return;
    int f = warp;
    float wa = w1[(f*4+0)*32 + lane];
    float wb = w1[(f*4+1)*32 + lane];
    float wc = w1[(f*4+2)*32 + lane];
    float wd = w1[(f*4+3)*32 + lane];
    #pragma unroll
    for (int v = 0; v < 9; v++) {
        int gi = f*9 + v;
        const float* e = emb + gi*4;
        float s = e[0]*wa + e[1]*wb + e[2]*wc + e[3]*wd;
        char* row = (char*)g_tbl + gi*ROWB;
        ((__half*)row)[lane] = __float2half_rn(s);
        if (lane == 0) *(float*)(row + 64) = w_lin[gi];
    }
}

// ---------------- mbarrier + TMA bulk helpers ----------------
__device__ __forceinline__ void mbar_init(unsigned m, unsigned cnt) {
    asm volatile("mbarrier.init.shared.b64 [%0], %1;" :: "r"(m), "r"(cnt) : "memory");
}
__device__ __forceinline__ void mbar_expect_tx(unsigned m, unsigned bytes) {
    asm volatile("mbarrier.arrive.expect_tx.shared.b64 _, [%0], %1;"
                 :: "r"(m), "r"(bytes) : "memory");
}
__device__ __forceinline__ void bulk_g2s(unsigned dst, const void* src,
                                         unsigned bytes, unsigned m) {
    asm volatile("cp.async.bulk.shared::cta.global.mbarrier::complete_tx::bytes "
                 "[%0], [%1], %2, [%3];"
                 :: "r"(dst), "l"(src), "r"(bytes), "r"(m) : "memory");
}
__device__ __forceinline__ void mbar_wait(unsigned m, unsigned parity) {
    asm volatile(
        "{\n\t.reg .pred P;\n"
        "WL%=:\n\t"
        "mbarrier.try_wait.parity.acquire.cta.shared::cta.b64 P, [%0], %1, 0x989680;\n\t"
        "@!P bra WL%=;\n\t}"
        :: "r"(m), "r"(parity) : "memory");
}

// reference semantics: x > 5.0 -> 8, else (int)(x + 2.0)
__device__ __forceinline__ int bucket(float x) {
    return (x > 5.0f) ? 8 : (int)(x + 2.0f);
}

// 4 gathers (one packed nibble group), batched loads then adds
#define G4(P, OFS) {                                                       \
    unsigned q0 = (P) & 15u, q1 = ((P)>>4) & 15u,                          \
             q2 = ((P)>>8) & 15u, q3 = ((P)>>12) & 15u;                    \
    uint2 d0 = *(const uint2*)(tbw + (OFS)        + q0*72);                \
    uint2 d1 = *(const uint2*)(tbw + (OFS) +  648 + q1*72);                \
    uint2 d2 = *(const uint2*)(tbw + (OFS) + 1296 + q2*72);                \
    uint2 d3 = *(const uint2*)(tbw + (OFS) + 1944 + q3*72);                \
    a0 = __hadd2(a0, *(const __half2*)&d0.x);                              \
    a1 = __hadd2(a1, *(const __half2*)&d0.y);                              \
    a2 = __hadd2(a2, *(const __half2*)&d1.x);                              \
    a3 = __hadd2(a3, *(const __half2*)&d1.y);                              \
    a0 = __hadd2(a0, *(const __half2*)&d2.x);                              \
    a1 = __hadd2(a1, *(const __half2*)&d2.y);                              \
    a2 = __hadd2(a2, *(const __half2*)&d3.x);                              \
    a3 = __hadd2(a3, *(const __half2*)&d3.y); }

__global__ void __launch_bounds__(512, 2)
fused_kernel(const float* __restrict__ state,
             const float* __restrict__ b1,  const float* __restrict__ g1,
             const float* __restrict__ be1,
             const float* __restrict__ w2,  const float* __restrict__ b2,
             const float* __restrict__ g2,  const float* __restrict__ be2,
             const float* __restrict__ w3,  const float* __restrict__ b3,
             const float* __restrict__ b_lin,
             float* __restrict__ out) {
    extern __shared__ char smem[];
    const int tid  = threadIdx.x;
    const int slot = tid & 63;        // sample within block
    const int g    = tid >> 6;        // output-eighth group 0..7
    const int s0   = blockIdx.x * 64;
    float* prm = (float*)(smem + PRM_OFF);
    const unsigned smem_u32 = (unsigned)__cvta_generic_to_shared(smem);
    const unsigned mbar0 = smem_u32 + MBAR_OFF;
    const unsigned mbar1 = smem_u32 + MBAR_OFF + 8;

    if (tid == 0) { mbar_init(mbar0, 1); mbar_init(mbar1, 1); }
    __syncthreads();
    // prefetch table chunks 0 and 1 via TMA bulk (overlaps staging below)
    if (tid == 0) {
        mbar_expect_tx(mbar0, TBL_CH);
        bulk_g2s(smem_u32, (const char*)g_tbl, TBL_CH, mbar0);
        mbar_expect_tx(mbar1, TBL_CH);
        bulk_g2s(smem_u32 + TBL_CH, (const char*)g_tbl + TBL_CH, TBL_CH, mbar1);
    }

    // stage idx chunk 0 (nibble-packed: float2 -> 1 byte)
    {
        char* dstb = smem + IDX_OFF;
        for (int e = tid; e < NELEM; e += 512) {
            int r = e / 29, u = e - r*29;
            float2 xv = *(const float2*)(state + (size_t)(s0 + r)*NF + u*2);
            dstb[r*IDXROW + u] =
                (char)(bucket(xv.x) | (bucket(xv.y) << 4));
        }
    }
    // stage MLP params
    for (int i = tid; i < 1154; i += 512) {
        float v;
        if (i < 1024)      v = w2[i];
        else if (i < 1056) v = b2[i-1024];
        else if (i < 1088) v = g2[i-1056];
        else if (i < 1120) v = be2[i-1088];
        else if (i < 1152) v = w3[i-1120];
        else if (i == 1152) v = b3[0];
        else               v = b_lin[0];
        prm[i] = v;
    }
    __syncthreads();

    __half2 a0 = __float2half2_rn(0.f), a1 = a0, a2 = a0, a3 = a0;
    float lin = 0.f;

    for (int c = 0; c < NCH; c++) {
        // stage idx for chunk c+1 (LDGs issue early; other CTA hides the rest)
        if (c + 1 < NCH) {
            char* dstb = smem + IDX_OFF + ((c+1)&1)*IDXBUF;
            const float* sbase = state + (size_t)s0*NF + (c+1)*CH;
            for (int e = tid; e < NELEM; e += 512) {
                int r = e / 29, u = e - r*29;
                float2 xv = *(const float2*)(sbase + (size_t)r*NF + u*2);
                dstb[r*IDXROW + u] =
                    (char)(bucket(xv.x) | (bucket(xv.y) << 4));
            }
        }

        // wait for this chunk's table transfer
        mbar_wait((c&1) ? mbar1 : mbar0, (c>>1)&1);

        const char* tbuf = smem + (c&1)*TBL_CH;
        const unsigned int* mi =
            (const unsigned int*)(smem + IDX_OFF + (c&1)*IDXBUF + slot*IDXROW);

        // gather: 7 full words (8 fields each) + tail byte (2 fields)
        {
            const char* tbw = tbuf + g*8;
            #pragma unroll 2
            for (int w = 0; w < 7; w++) {
                unsigned int pk = mi[w];
                G4(pk, 0);
                G4(pk >> 16, 2592);
                tbw += 5184;
            }
            unsigned int pk = mi[7];       // low byte valid: fields 56,57
            uint2 d0 = *(const uint2*)(tbw + (pk & 15u)*72);
            uint2 d1 = *(const uint2*)(tbw + 648 + ((pk >> 4) & 15u)*72);
            a0 = __hadd2(a0, *(const __half2*)&d0.x);
            a1 = __hadd2(a1, *(const __half2*)&d0.y);
            a2 = __hadd2(a2, *(const __half2*)&d1.x);
            a3 = __hadd2(a3, *(const __half2*)&d1.y);
        }

        // lin accumulation: 29 bytes split across 8 groups (5x4 + 3x3)
        {
            const unsigned char* bi = (const unsigned char*)mi;
            int lo = (g < 5) ? g*4 : 20 + (g-5)*3;
            int nb = (g < 5) ? 4 : 3;
            for (int b = lo; b < lo + nb; b++) {
                unsigned int pkb = bi[b];
                const char* fb = tbuf + b*1296 + 64;
                lin += *(const float*)(fb + (pkb & 15u)*72);
                lin += *(const float*)(fb + 648 + (pkb >> 4)*72);
            }
        }

        __syncthreads();   // idx(c+1) visible; table buf (c&1) drained

        // refill this table buffer with chunk c+2
        if (tid == 0 && c + 2 < NCH) {
            unsigned mb = (c&1) ? mbar1 : mbar0;
            mbar_expect_tx(mb, TBL_CH);
            bulk_g2s(smem_u32 + (c&1)*TBL_CH,
                     (const char*)g_tbl + (c+2)*TBL_CH, TBL_CH, mb);
        }
    }

    // ---------------- epilogue: BN1+ReLU, MLP, sigmoid ----------------
    a0 = __hadd2(a0, a2);
    a1 = __hadd2(a1, a3);
    float2 p01 = __half22float2(a0);
    float2 p23 = __half22float2(a1);
    float pre[4] = {p01.x, p01.y, p23.x, p23.y};
    float* h1b = (float*)smem;               // reuse table region: [64][41]
    const int j0 = g*4;
    #pragma unroll
    for (int k = 0; k < 4; k++) {
        int j = j0 + k;
        float sc = g1[j] * BN_INV;
        float h  = pre[k]*sc + (b1[j]*sc + be1[j]);
        h1b[slot*41 + j] = fmaxf(h, 0.f);
    }
    h1b[slot*41 + 32 + g] = lin;
    __syncthreads();

    if (tid < 64) {
        const float* hr = h1b + tid*41;
        float linv = 0.f;
        #pragma unroll
        for (int i = 0; i < 8; i++) linv += hr[32 + i];
        float acc[32];
        #pragma unroll
        for (int j = 0; j < 32; j++) acc[j] = prm[1024 + j];   // b2
        for (int k = 0; k < 32; k++) {
            float xk = hr[k];
            #pragma unroll
            for (int j = 0; j < 32; j++) acc[j] += xk * prm[k*32 + j];  // w2
        }
        float x = prm[1152] + prm[1153] + linv;   // b3 + b_lin + lin
        #pragma unroll
        for (int j = 0; j < 32; j++) {
            float h2 = fmaxf(acc[j]*(prm[1056+j]*BN_INV) + prm[1088+j], 0.f);
            x += h2 * prm[1120+j];                // w3
        }
        out[s0 + tid] = 1.0f / (1.0f + expf(-x));
    }
}

// ---------------- launch ----------------
extern "C" void kernel_launch(void* const* d_in, const int* in_sizes, int n_in,
                              void* d_out, int out_size) {
    const float* state = (const float*)d_in[0];
    const float* w_lin = (const float*)d_in[1];
    const float* b_lin = (const float*)d_in[2];
    const float* emb   = (const float*)d_in[3];
    const float* w1    = (const float*)d_in[4];
    const float* b1    = (const float*)d_in[5];
    const float* g1    = (const float*)d_in[6];
    const float* be1   = (const float*)d_in[7];
    const float* w2    = (const float*)d_in[8];
    const float* b2    = (const float*)d_in[9];
    const float* g2    = (const float*)d_in[10];
    const float* be2   = (const float*)d_in[11];
    const float* w3    = (const float*)d_in[12];
    const float* b3    = (const float*)d_in[13];
    float* out = (float*)d_out;

    cudaFuncSetAttribute(fused_kernel,
                         cudaFuncAttributeMaxDynamicSharedMemorySize, SMEM_SZ);

    build_table<<<131, 256>>>(emb, w1, w_lin);
    fused_kernel<<<256, 512, SMEM_SZ>>>(state, b1, g1, be1,
                                        w2, b2, g2, be2, w3, b3, b_lin, out);
}

// round 10
// speedup vs baseline: 1.1613x; 1.0973x over previous
#include <cuda_runtime.h>
#include <cuda_fp16.h>
#include <math.h>

// ---------------- problem constants ----------------
#define NF     1044
#define VOCAB  9396                 // NF * 9
#define CH     116                  // fields per chunk (1044 = 9*116) = 29 float4
#define NCH    9
#define ROWB   72                   // 32 fp16 + fp32 lin + 4B pad
#define FSTRIDE 648                 // 9*ROWB
#define TBL_CH (CH*FSTRIDE)         // 75168 bytes per chunk
#define IDX_OFF (2*TBL_CH)          // 150336
#define IDXROW  60                  // bytes per sample per chunk (58 used)
#define IDXBUF  (128*IDXROW)        // 7680
#define MBAR_OFF (IDX_OFF + 2*IDXBUF)      // 165696 (16-aligned)
#define PRM_OFF  (MBAR_OFF + 16)           // 165712
#define SMEM_SZ  (PRM_OFF + 4624)          // 170336
#define SPC     111                        // samples per CTA (148*111 >= 16384)
#define BATCH   16384
#define BN_INV  0.9999950000374997f        // 1/sqrt(1+1e-5)

// fused table: [VOCAB][72B] = {32 x fp16 (emb row @ w1 block), fp32 w_lin, pad}
__device__ __align__(16) unsigned char g_tbl[VOCAB * ROWB];

// ---------------- pass 0: build fused table ----------------
__global__ void build_table(const float* __restrict__ emb,
                            const float* __restrict__ w1,
                            const float* __restrict__ w_lin) {
    int warp = (blockIdx.x * blockDim.x + threadIdx.x) >> 5;
    int lane = threadIdx.x & 31;
    if (warp >= NF) return;
    int f = warp;
    float wa = w1[(f*4+0)*32 + lane];
    float wb = w1[(f*4+1)*32 + lane];
    float wc = w1[(f*4+2)*32 + lane];
    float wd = w1[(f*4+3)*32 + lane];
    #pragma unroll
    for (int v = 0; v < 9; v++) {
        int gi = f*9 + v;
        const float* e = emb + gi*4;
        float s = e[0]*wa + e[1]*wb + e[2]*wc + e[3]*wd;
        char* row = (char*)g_tbl + gi*ROWB;
        ((__half*)row)[lane] = __float2half_rn(s);
        if (lane == 0) *(float*)(row + 64) = w_lin[gi];
    }
}

// ---------------- mbarrier + TMA bulk helpers ----------------
__device__ __forceinline__ void mbar_init(unsigned m, unsigned cnt) {
    asm volatile("mbarrier.init.shared.b64 [%0], %1;" :: "r"(m), "r"(cnt) : "memory");
}
__device__ __forceinline__ void mbar_expect_tx(unsigned m, unsigned bytes) {
    asm volatile("mbarrier.arrive.expect_tx.shared.b64 _, [%0], %1;"
                 :: "r"(m), "r"(bytes) : "memory");
}
__device__ __forceinline__ void bulk_g2s(unsigned dst, const void* src,
                                         unsigned bytes, unsigned m) {
    asm volatile("cp.async.bulk.shared::cta.global.mbarrier::complete_tx::bytes "
                 "[%0], [%1], %2, [%3];"
                 :: "r"(dst), "l"(src), "r"(bytes), "r"(m) : "memory");
}
__device__ __forceinline__ void mbar_wait(unsigned m, unsigned parity) {
    asm volatile(
        "{\n\t.reg .pred P;\n"
        "WL%=:\n\t"
        "mbarrier.try_wait.parity.acquire.cta.shared::cta.b64 P, [%0], %1, 0x989680;\n\t"
        "@!P bra WL%=;\n\t}"
        :: "r"(m), "r"(parity) : "memory");
}

// reference semantics: x > 5.0 -> 8, else (int)(x + 2.0)
__device__ __forceinline__ int bucket(float x) {
    return (x > 5.0f) ? 8 : (int)(x + 2.0f);
}

// 4 gathers (one packed nibble group), batched loads then adds
#define G4(P, OFS) {                                                       \
    unsigned q0 = (P) & 15u, q1 = ((P)>>4) & 15u,                          \
             q2 = ((P)>>8) & 15u, q3 = ((P)>>12) & 15u;                    \
    uint2 d0 = *(const uint2*)(tbw + (OFS)        + q0*72);                \
    uint2 d1 = *(const uint2*)(tbw + (OFS) +  648 + q1*72);                \
    uint2 d2 = *(const uint2*)(tbw + (OFS) + 1296 + q2*72);                \
    uint2 d3 = *(const uint2*)(tbw + (OFS) + 1944 + q3*72);                \
    a0 = __hadd2(a0, *(const __half2*)&d0.x);                              \
    a1 = __hadd2(a1, *(const __half2*)&d0.y);                              \
    a2 = __hadd2(a2, *(const __half2*)&d1.x);                              \
    a3 = __hadd2(a3, *(const __half2*)&d1.y);                              \
    a0 = __hadd2(a0, *(const __half2*)&d2.x);                              \
    a1 = __hadd2(a1, *(const __half2*)&d2.y);                              \
    a2 = __hadd2(a2, *(const __half2*)&d3.x);                              \
    a3 = __hadd2(a3, *(const __half2*)&d3.y); }

__global__ void __launch_bounds__(1024, 1)
fused_kernel(const float* __restrict__ state,
             const float* __restrict__ b1,  const float* __restrict__ g1,
             const float* __restrict__ be1,
             const float* __restrict__ w2,  const float* __restrict__ b2,
             const float* __restrict__ g2,  const float* __restrict__ be2,
             const float* __restrict__ w3,  const float* __restrict__ b3,
             const float* __restrict__ b_lin,
             float* __restrict__ out) {
    extern __shared__ char smem[];
    const int tid  = threadIdx.x;
    const int slot = tid & 127;       // sample within block
    const int g    = tid >> 7;        // output-eighth group 0..7
    const int s0   = blockIdx.x * SPC;
    const int ns   = min(SPC, BATCH - s0);   // samples this CTA owns
    const int nelem = ns * 29;               // float4 elements per chunk slice
    float* prm = (float*)(smem + PRM_OFF);
    const unsigned smem_u32 = (unsigned)__cvta_generic_to_shared(smem);
    const unsigned mbar0 = smem_u32 + MBAR_OFF;
    const unsigned mbar1 = smem_u32 + MBAR_OFF + 8;

    if (tid == 0) { mbar_init(mbar0, 1); mbar_init(mbar1, 1); }
    __syncthreads();
    // prefetch table chunks 0 and 1 via TMA bulk (overlaps staging below)
    if (tid == 0) {
        mbar_expect_tx(mbar0, TBL_CH);
        bulk_g2s(smem_u32, (const char*)g_tbl, TBL_CH, mbar0);
        mbar_expect_tx(mbar1, TBL_CH);
        bulk_g2s(smem_u32 + TBL_CH, (const char*)g_tbl + TBL_CH, TBL_CH, mbar1);
    }

    // stage idx chunk 0 (nibble-packed: float4 -> uint16)
    {
        char* dstb = smem + IDX_OFF;
        for (int e = tid; e < nelem; e += 1024) {
            int r = e / 29, u = e - r*29;
            float4 xv = *(const float4*)(state + (size_t)(s0 + r)*NF + u*4);
            int v0 = bucket(xv.x), v1 = bucket(xv.y);
            int v2 = bucket(xv.z), v3 = bucket(xv.w);
            *(unsigned short*)(dstb + r*IDXROW + u*2) =
                (unsigned short)(v0 | (v1<<4) | (v2<<8) | (v3<<12));
        }
    }
    // stage MLP params
    for (int i = tid; i < 1154; i += 1024) {
        float v;
        if (i < 1024)      v = w2[i];
        else if (i < 1056) v = b2[i-1024];
        else if (i < 1088) v = g2[i-1056];
        else if (i < 1120) v = be2[i-1088];
        else if (i < 1152) v = w3[i-1120];
        else if (i == 1152) v = b3[0];
        else               v = b_lin[0];
        prm[i] = v;
    }
    __syncthreads();

    __half2 a0 = __float2half2_rn(0.f), a1 = a0, a2 = a0, a3 = a0;
    float lin = 0.f;

    for (int c = 0; c < NCH; c++) {
        // stage idx for chunk c+1 (LDGs issue early, latency hides under gather)
        if (c + 1 < NCH) {
            char* dstb = smem + IDX_OFF + ((c+1)&1)*IDXBUF;
            const float* sbase = state + (size_t)s0*NF + (c+1)*CH;
            for (int e = tid; e < nelem; e += 1024) {
                int r = e / 29, u = e - r*29;
                float4 xv = *(const float4*)(sbase + (size_t)r*NF + u*4);
                int v0 = bucket(xv.x), v1 = bucket(xv.y);
                int v2 = bucket(xv.z), v3 = bucket(xv.w);
                *(unsigned short*)(dstb + r*IDXROW + u*2) =
                    (unsigned short)(v0 | (v1<<4) | (v2<<8) | (v3<<12));
            }
        }

        // wait for this chunk's table transfer
        mbar_wait((c&1) ? mbar1 : mbar0, (c>>1)&1);

        const char* tbuf = smem + (c&1)*TBL_CH;
        const unsigned int* mi =
            (const unsigned int*)(smem + IDX_OFF + (c&1)*IDXBUF + slot*IDXROW);

        // gather: 14 full words (8 fields each) + tail half-word (4 fields)
        // slots >= ns read stale idx nibbles (0..15): offsets stay inside smem.
        {
            const char* tbw = tbuf + g*8;
            #pragma unroll 2
            for (int w = 0; w < 14; w++) {
                unsigned int pk = mi[w];
                G4(pk, 0);
                G4(pk >> 16, 2592);
                tbw += 5184;
            }
            unsigned int pk = mi[14];
            G4(pk, 0);
        }

        // lin accumulation: bytes split across 8 groups (2x8 + 6x7 = 58)
        {
            const unsigned char* bi = (const unsigned char*)mi;
            int lo = (g < 2) ? g*8 : 16 + (g-2)*7;
            int nb = (g < 2) ? 8 : 7;
            for (int b = lo; b < lo + nb; b++) {
                unsigned int pkb = bi[b];
                const char* fb = tbuf + b*1296 + 64;
                lin += *(const float*)(fb + (pkb & 15u)*72);
                lin += *(const float*)(fb + 648 + (pkb >> 4)*72);
            }
        }

        __syncthreads();   // idx(c+1) visible; table buf (c&1) drained

        // refill this table buffer with chunk c+2
        if (tid == 0 && c + 2 < NCH) {
            unsigned mb = (c&1) ? mbar1 : mbar0;
            mbar_expect_tx(mb, TBL_CH);
            bulk_g2s(smem_u32 + (c&1)*TBL_CH,
                     (const char*)g_tbl + (c+2)*TBL_CH, TBL_CH, mb);
        }
    }

    // ---------------- epilogue: BN1+ReLU, MLP, sigmoid ----------------
    a0 = __hadd2(a0, a2);
    a1 = __hadd2(a1, a3);
    float2 p01 = __half22float2(a0);
    float2 p23 = __half22float2(a1);
    float pre[4] = {p01.x, p01.y, p23.x, p23.y};
    float* h1b = (float*)smem;               // reuse table region: [128][41]
    const int j0 = g*4;
    #pragma unroll
    for (int k = 0; k < 4; k++) {
        int j = j0 + k;
        float sc = g1[j] * BN_INV;
        float h  = pre[k]*sc + (b1[j]*sc + be1[j]);
        h1b[slot*41 + j] = fmaxf(h, 0.f);
    }
    h1b[slot*41 + 32 + g] = lin;
    __syncthreads();

    if (tid < ns) {
        const float* hr = h1b + tid*41;
        float linv = 0.f;
        #pragma unroll
        for (int i = 0; i < 8; i++) linv += hr[32 + i];
        float acc[32];
        #pragma unroll
        for (int j = 0; j < 32; j++) acc[j] = prm[1024 + j];   // b2
        for (int k = 0; k < 32; k++) {
            float xk = hr[k];
            #pragma unroll
            for (int j = 0; j < 32; j++) acc[j] += xk * prm[k*32 + j];  // w2
        }
        float x = prm[1152] + prm[1153] + linv;   // b3 + b_lin + lin
        #pragma unroll
        for (int j = 0; j < 32; j++) {
            float h2 = fmaxf(acc[j]*(prm[1056+j]*BN_INV) + prm[1088+j], 0.f);
            x += h2 * prm[1120+j];                // w3
        }
        out[s0 + tid] = 1.0f / (1.0f + expf(-x));
    }
}

// ---------------- launch ----------------
extern "C" void kernel_launch(void* const* d_in, const int* in_sizes, int n_in,
                              void* d_out, int out_size) {
    const float* state = (const float*)d_in[0];
    const float* w_lin = (const float*)d_in[1];
    const float* b_lin = (const float*)d_in[2];
    const float* emb   = (const float*)d_in[3];
    const float* w1    = (const float*)d_in[4];
    const float* b1    = (const float*)d_in[5];
    const float* g1    = (const float*)d_in[6];
    const float* be1   = (const float*)d_in[7];
    const float* w2    = (const float*)d_in[8];
    const float* b2    = (const float*)d_in[9];
    const float* g2    = (const float*)d_in[10];
    const float* be2   = (const float*)d_in[11];
    const float* w3    = (const float*)d_in[12];
    const float* b3    = (const float*)d_in[13];
    float* out = (float*)d_out;

    cudaFuncSetAttribute(fused_kernel,
                         cudaFuncAttributeMaxDynamicSharedMemorySize, SMEM_SZ);

    build_table<<<131, 256>>>(emb, w1, w_lin);
    fused_kernel<<<148, 1024, SMEM_SZ>>>(state, b1, g1, be1,
                                         w2, b2, g2, be2, w3, b3, b_lin, out);
}

// round 11
// speedup vs baseline: 1.1785x; 1.0148x over previous
#include <cuda_runtime.h>
#include <cuda_fp16.h>
#include <math.h>

// ---------------- problem constants ----------------
#define NF     1044
#define VOCAB  9396                 // NF * 9
#define CH     116                  // fields per chunk (1044 = 9*116) = 29 float4
#define NCH    9
#define ROWB   72                   // 32 fp16 + fp32 lin + 4B pad
#define FSTRIDE 648                 // 9*ROWB
#define TBL_CH (CH*FSTRIDE)         // 75168 bytes per chunk
#define IDX_OFF (2*TBL_CH)          // 150336
#define IDXROW  60                  // bytes per sample per chunk (58 used)
#define IDXBUF  (128*IDXROW)        // 7680
#define MBAR_OFF (IDX_OFF + 2*IDXBUF)      // 165696 (16-aligned)
#define PRM_OFF  (MBAR_OFF + 16)           // 165712
#define SMEM_SZ  (PRM_OFF + 4624)          // 170336
#define SPC     111                        // samples per CTA (148*111 >= 16384)
#define BATCH   16384
#define BN_INV  0.9999950000374997f        // 1/sqrt(1+1e-5)

// fused table: [VOCAB][72B] = {32 x fp16 (emb row @ w1 block), fp32 w_lin, pad}
__device__ __align__(16) unsigned char g_tbl[VOCAB * ROWB];

// ---------------- pass 0: build fused table ----------------
__global__ void build_table(const float* __restrict__ emb,
                            const float* __restrict__ w1,
                            const float* __restrict__ w_lin) {
    int warp = (blockIdx.x * blockDim.x + threadIdx.x) >> 5;
    int lane = threadIdx.x & 31;
    if (warp >= NF) return;
    int f = warp;
    float wa = w1[(f*4+0)*32 + lane];
    float wb = w1[(f*4+1)*32 + lane];
    float wc = w1[(f*4+2)*32 + lane];
    float wd = w1[(f*4+3)*32 + lane];
    #pragma unroll
    for (int v = 0; v < 9; v++) {
        int gi = f*9 + v;
        const float* e = emb + gi*4;
        float s = e[0]*wa + e[1]*wb + e[2]*wc + e[3]*wd;
        char* row = (char*)g_tbl + gi*ROWB;
        ((__half*)row)[lane] = __float2half_rn(s);
        if (lane == 0) *(float*)(row + 64) = w_lin[gi];
    }
}

// ---------------- mbarrier + TMA bulk helpers ----------------
__device__ __forceinline__ void mbar_init(unsigned m, unsigned cnt) {
    asm volatile("mbarrier.init.shared.b64 [%0], %1;" :: "r"(m), "r"(cnt) : "memory");
}
__device__ __forceinline__ void mbar_expect_tx(unsigned m, unsigned bytes) {
    asm volatile("mbarrier.arrive.expect_tx.shared.b64 _, [%0], %1;"
                 :: "r"(m), "r"(bytes) : "memory");
}
__device__ __forceinline__ void bulk_g2s(unsigned dst, const void* src,
                                         unsigned bytes, unsigned m) {
    asm volatile("cp.async.bulk.shared::cta.global.mbarrier::complete_tx::bytes "
                 "[%0], [%1], %2, [%3];"
                 :: "r"(dst), "l"(src), "r"(bytes), "r"(m) : "memory");
}
__device__ __forceinline__ void mbar_wait(unsigned m, unsigned parity) {
    asm volatile(
        "{\n\t.reg .pred P;\n"
        "WL%=:\n\t"
        "mbarrier.try_wait.parity.acquire.cta.shared::cta.b64 P, [%0], %1, 0x989680;\n\t"
        "@!P bra WL%=;\n\t}"
        :: "r"(m), "r"(parity) : "memory");
}

// reference semantics: x > 5.0 -> 8, else (int)(x + 2.0)
__device__ __forceinline__ int bucket(float x) {
    return (x > 5.0f) ? 8 : (int)(x + 2.0f);
}

// 4 gathers (one packed nibble group), batched loads then adds
#define G4(P, OFS) {                                                       \
    unsigned q0 = (P) & 15u, q1 = ((P)>>4) & 15u,                          \
             q2 = ((P)>>8) & 15u, q3 = ((P)>>12) & 15u;                    \
    uint2 d0 = *(const uint2*)(tbw + (OFS)        + q0*72);                \
    uint2 d1 = *(const uint2*)(tbw + (OFS) +  648 + q1*72);                \
    uint2 d2 = *(const uint2*)(tbw + (OFS) + 1296 + q2*72);                \
    uint2 d3 = *(const uint2*)(tbw + (OFS) + 1944 + q3*72);                \
    a0 = __hadd2(a0, *(const __half2*)&d0.x);                              \
    a1 = __hadd2(a1, *(const __half2*)&d0.y);                              \
    a2 = __hadd2(a2, *(const __half2*)&d1.x);                              \
    a3 = __hadd2(a3, *(const __half2*)&d1.y);                              \
    a0 = __hadd2(a0, *(const __half2*)&d2.x);                              \
    a1 = __hadd2(a1, *(const __half2*)&d2.y);                              \
    a2 = __hadd2(a2, *(const __half2*)&d3.x);                              \
    a3 = __hadd2(a3, *(const __half2*)&d3.y); }

__global__ void __launch_bounds__(1024, 1)
fused_kernel(const float* __restrict__ state,
             const float* __restrict__ b1,  const float* __restrict__ g1,
             const float* __restrict__ be1,
             const float* __restrict__ w2,  const float* __restrict__ b2,
             const float* __restrict__ g2,  const float* __restrict__ be2,
             const float* __restrict__ w3,  const float* __restrict__ b3,
             const float* __restrict__ b_lin,
             float* __restrict__ out) {
    extern __shared__ char smem[];
    const int tid  = threadIdx.x;
    const int slot = tid & 127;       // sample within block
    const int g    = tid >> 7;        // output-eighth group 0..7
    const int s0   = blockIdx.x * SPC;
    const int ns   = min(SPC, BATCH - s0);   // samples this CTA owns
    const int nelem = ns * 29;               // float4 elements per chunk slice
    const bool live = (slot < ns);           // this lane maps to a real sample
    float* prm = (float*)(smem + PRM_OFF);
    const unsigned smem_u32 = (unsigned)__cvta_generic_to_shared(smem);
    const unsigned mbar0 = smem_u32 + MBAR_OFF;
    const unsigned mbar1 = smem_u32 + MBAR_OFF + 8;

    if (tid == 0) { mbar_init(mbar0, 1); mbar_init(mbar1, 1); }
    __syncthreads();
    // prefetch table chunks 0 and 1 via TMA bulk (overlaps staging below)
    if (tid == 0) {
        mbar_expect_tx(mbar0, TBL_CH);
        bulk_g2s(smem_u32, (const char*)g_tbl, TBL_CH, mbar0);
        mbar_expect_tx(mbar1, TBL_CH);
        bulk_g2s(smem_u32 + TBL_CH, (const char*)g_tbl + TBL_CH, TBL_CH, mbar1);
    }

    // stage idx chunk 0 (nibble-packed: float4 -> uint16)
    {
        char* dstb = smem + IDX_OFF;
        for (int e = tid; e < nelem; e += 1024) {
            int r = e / 29, u = e - r*29;
            float4 xv = *(const float4*)(state + (size_t)(s0 + r)*NF + u*4);
            int v0 = bucket(xv.x), v1 = bucket(xv.y);
            int v2 = bucket(xv.z), v3 = bucket(xv.w);
            *(unsigned short*)(dstb + r*IDXROW + u*2) =
                (unsigned short)(v0 | (v1<<4) | (v2<<8) | (v3<<12));
        }
    }
    // stage MLP params
    for (int i = tid; i < 1154; i += 1024) {
        float v;
        if (i < 1024)      v = w2[i];
        else if (i < 1056) v = b2[i-1024];
        else if (i < 1088) v = g2[i-1056];
        else if (i < 1120) v = be2[i-1088];
        else if (i < 1152) v = w3[i-1120];
        else if (i == 1152) v = b3[0];
        else               v = b_lin[0];
        prm[i] = v;
    }
    __syncthreads();

    __half2 a0 = __float2half2_rn(0.f), a1 = a0, a2 = a0, a3 = a0;
    float lin = 0.f;

    for (int c = 0; c < NCH; c++) {
        // stage idx for chunk c+1 (LDGs issue early, latency hides under gather)
        if (c + 1 < NCH) {
            char* dstb = smem + IDX_OFF + ((c+1)&1)*IDXBUF;
            const float* sbase = state + (size_t)s0*NF + (c+1)*CH;
            for (int e = tid; e < nelem; e += 1024) {
                int r = e / 29, u = e - r*29;
                float4 xv = *(const float4*)(sbase + (size_t)r*NF + u*4);
                int v0 = bucket(xv.x), v1 = bucket(xv.y);
                int v2 = bucket(xv.z), v3 = bucket(xv.w);
                *(unsigned short*)(dstb + r*IDXROW + u*2) =
                    (unsigned short)(v0 | (v1<<4) | (v2<<8) | (v3<<12));
            }
        }

        // wait for this chunk's table transfer
        mbar_wait((c&1) ? mbar1 : mbar0, (c>>1)&1);

        // stale slots (>= ns) skip the gather entirely: their lanes are
        // predicated off, freeing crossbar wavefront slots + issue slots.
        if (live) {
            const char* tbuf = smem + (c&1)*TBL_CH;
            const unsigned int* mi =
                (const unsigned int*)(smem + IDX_OFF + (c&1)*IDXBUF + slot*IDXROW);

            // gather: 14 full words (8 fields each) + tail half-word (4 fields)
            {
                const char* tbw = tbuf + g*8;
                #pragma unroll 2
                for (int w = 0; w < 14; w++) {
                    unsigned int pk = mi[w];
                    G4(pk, 0);
                    G4(pk >> 16, 2592);
                    tbw += 5184;
                }
                unsigned int pk = mi[14];
                G4(pk, 0);
            }

            // lin accumulation: bytes split across 8 groups (2x8 + 6x7 = 58)
            {
                const unsigned char* bi = (const unsigned char*)mi;
                int lo = (g < 2) ? g*8 : 16 + (g-2)*7;
                int nb = (g < 2) ? 8 : 7;
                for (int b = lo; b < lo + nb; b++) {
                    unsigned int pkb = bi[b];
                    const char* fb = tbuf + b*1296 + 64;
                    lin += *(const float*)(fb + (pkb & 15u)*72);
                    lin += *(const float*)(fb + 648 + (pkb >> 4)*72);
                }
            }
        }

        __syncthreads();   // idx(c+1) visible; table buf (c&1) drained

        // refill this table buffer with chunk c+2
        if (tid == 0 && c + 2 < NCH) {
            unsigned mb = (c&1) ? mbar1 : mbar0;
            mbar_expect_tx(mb, TBL_CH);
            bulk_g2s(smem_u32 + (c&1)*TBL_CH,
                     (const char*)g_tbl + (c+2)*TBL_CH, TBL_CH, mb);
        }
    }

    // ---------------- epilogue: BN1+ReLU, MLP, sigmoid ----------------
    a0 = __hadd2(a0, a2);
    a1 = __hadd2(a1, a3);
    float2 p01 = __half22float2(a0);
    float2 p23 = __half22float2(a1);
    float pre[4] = {p01.x, p01.y, p23.x, p23.y};
    float* h1b = (float*)smem;               // reuse table region: [128][41]
    const int j0 = g*4;
    #pragma unroll
    for (int k = 0; k < 4; k++) {
        int j = j0 + k;
        float sc = g1[j] * BN_INV;
        float h  = pre[k]*sc + (b1[j]*sc + be1[j]);
        h1b[slot*41 + j] = fmaxf(h, 0.f);
    }
    h1b[slot*41 + 32 + g] = lin;
    __syncthreads();

    if (tid < ns) {
        const float* hr = h1b + tid*41;
        float linv = 0.f;
        #pragma unroll
        for (int i = 0; i < 8; i++) linv += hr[32 + i];
        float acc[32];
        #pragma unroll
        for (int j = 0; j < 32; j++) acc[j] = prm[1024 + j];   // b2
        for (int k = 0; k < 32; k++) {
            float xk = hr[k];
            #pragma unroll
            for (int j = 0; j < 32; j++) acc[j] += xk * prm[k*32 + j];  // w2
        }
        float x = prm[1152] + prm[1153] + linv;   // b3 + b_lin + lin
        #pragma unroll
        for (int j = 0; j < 32; j++) {
            float h2 = fmaxf(acc[j]*(prm[1056+j]*BN_INV) + prm[1088+j], 0.f);
            x += h2 * prm[1120+j];                // w3
        }
        out[s0 + tid] = 1.0f / (1.0f + expf(-x));
    }
}

// ---------------- launch ----------------
extern "C" void kernel_launch(void* const* d_in, const int* in_sizes, int n_in,
                              void* d_out, int out_size) {
    const float* state = (const float*)d_in[0];
    const float* w_lin = (const float*)d_in[1];
    const float* b_lin = (const float*)d_in[2];
    const float* emb   = (const float*)d_in[3];
    const float* w1    = (const float*)d_in[4];
    const float* b1    = (const float*)d_in[5];
    const float* g1    = (const float*)d_in[6];
    const float* be1   = (const float*)d_in[7];
    const float* w2    = (const float*)d_in[8];
    const float* b2    = (const float*)d_in[9];
    const float* g2    = (const float*)d_in[10];
    const float* be2   = (const float*)d_in[11];
    const float* w3    = (const float*)d_in[12];
    const float* b3    = (const float*)d_in[13];
    float* out = (float*)d_out;

    cudaFuncSetAttribute(fused_kernel,
                         cudaFuncAttributeMaxDynamicSharedMemorySize, SMEM_SZ);

    build_table<<<131, 256>>>(emb, w1, w_lin);
    fused_kernel<<<148, 1024, SMEM_SZ>>>(state, b1, g1, be1,
                                         w2, b2, g2, be2, w3, b3, b_lin, out);
}